// round 10
// baseline (speedup 1.0000x reference)
#include <cuda_runtime.h>
#include <cstdint>

#define BB   2
#define NN   16384
#define SS   4096
#define KK   32
#define FIN  16
#define MTOT (BB*SS)      /* 8192 centers */
#define BN   (BB*NN)      /* 32768 points */
#define NCELL 1000        /* 10x10x10 cells of size R=0.1 per cloud */
#define R2   0.01f

// ---------------- device scratch (no runtime allocation allowed) ----------------
__device__ float  g_posx[BN], g_posy[BN], g_posz[BN];
__device__ int    g_sidx[MTOT];                 // selected local point idx per (b,s)
__device__ float  g_cx[MTOT], g_cy[MTOT], g_cz[MTOT];
__device__ int    g_cellCnt[BB*NCELL];
__device__ int    g_cellStart[BB*NCELL];
__device__ int    g_cellCur[BB*NCELL];
__device__ int    g_cellPts[BN];
__device__ float  g_opx[BN], g_opy[BN], g_opz[BN];  // cell-ordered positions
__device__ int    g_opid[BN];                        // cell-ordered -> local point id
__device__ float4 g_pts[BN];                         // fused {x, y, z, bits(pid)}
__device__ float  g_xw[BN*64];                  // x @ W1[:16] + b1   (8 MB)
__device__ int    g_nbr[MTOT*KK];
__device__ int    g_cnt[MTOT];

// ---------------- prep: SoA split of pos + zero cell counts ----------------
__global__ void prep_kernel(const float* __restrict__ pos) {
    int i = blockIdx.x * blockDim.x + threadIdx.x;
    if (i < BN) {
        g_posx[i] = pos[3*i+0];
        g_posy[i] = pos[3*i+1];
        g_posz[i] = pos[3*i+2];
    }
    if (i < BB*NCELL) g_cellCnt[i] = 0;
}

__device__ __forceinline__ int cell_of(float px, float py, float pz, int b) {
    int cx = (int)(px * 10.0f); cx = cx < 0 ? 0 : (cx > 9 ? 9 : cx);
    int cy = (int)(py * 10.0f); cy = cy < 0 ? 0 : (cy > 9 ? 9 : cy);
    int cz = (int)(pz * 10.0f); cz = cz < 0 ? 0 : (cz > 9 ? 9 : cz);
    return b * NCELL + (cz * 10 + cy) * 10 + cx;
}

__global__ void count_kernel() {
    int i = blockIdx.x * blockDim.x + threadIdx.x;
    if (i >= BN) return;
    int b = i >> 14;
    atomicAdd(&g_cellCnt[cell_of(g_posx[i], g_posy[i], g_posz[i], b)], 1);
}

// single-warp exclusive scan over 2000 cells
__global__ void scan_kernel() {
    int lane = threadIdx.x;
    int acc = 0;
    for (int base = 0; base < BB*NCELL; base += 32) {
        int idx = base + lane;
        int v = (idx < BB*NCELL) ? g_cellCnt[idx] : 0;
        int inc = v;
        #pragma unroll
        for (int o = 1; o < 32; o <<= 1) {
            int n = __shfl_up_sync(0xffffffffu, inc, o);
            if (lane >= o) inc += n;
        }
        if (idx < BB*NCELL) {
            g_cellStart[idx] = acc + inc - v;
            g_cellCur[idx]   = acc + inc - v;
        }
        acc += __shfl_sync(0xffffffffu, inc, 31);
    }
}

__global__ void scatter_kernel() {
    int i = blockIdx.x * blockDim.x + threadIdx.x;
    if (i >= BN) return;
    int b = i >> 14;
    int cid = cell_of(g_posx[i], g_posy[i], g_posz[i], b);
    int slot = atomicAdd(&g_cellCur[cid], 1);
    g_cellPts[slot] = i & (NN - 1);   // local index within cloud
}

// build cell-ordered arrays: SoA pos (ballq), fused float4 (FPS), id map
__global__ void gather_kernel() {
    int i = blockIdx.x * blockDim.x + threadIdx.x;
    if (i >= BN) return;
    int b = i >> 14;                 // slots of cloud b occupy [b*NN, (b+1)*NN)
    int pid = g_cellPts[i];
    int gp = b*NN + pid;
    float px = g_posx[gp], py = g_posy[gp], pz = g_posz[gp];
    g_opx[i] = px;
    g_opy[i] = py;
    g_opz[i] = pz;
    g_opid[i] = pid;
    g_pts[i] = make_float4(px, py, pz, __int_as_float(pid));
}

// ---------------- FPS: thread-owns-16-points chunks, AABB prune, 1 barrier/iter ----
// per-point key (u64): dminbits[32] << 24 | invpid[14] << 10 | i[4]
//   dmin >= 0 -> float bits u32-monotone; invpid = 0x3FFF - pid -> max key = (dmin desc, pid asc)
#define FPS6_SMEM (NN*8 + NN*4 + 64*4 + 64*4 + 16)

__global__ void __launch_bounds__(1024, 1) fps_chunk_kernel() {
    extern __shared__ float sm[];
    float2*   sxy = (float2*)sm;                 // NN
    float*    sz  = (float*)(sxy + NN);          // NN
    unsigned* swd = (unsigned*)(sz + NN);        // 2 x 32 (double-buffered warp dmin bits)
    unsigned* swq = swd + 64;                    // 2 x 32 (double-buffered invpid<<14|slot)
    int*      sslot0 = (int*)(swq + 64);

    const int b    = blockIdx.x;
    const int tid  = threadIdx.x;
    const int wid  = tid >> 5;
    const int lane = tid & 31;
    const int base = tid * 16;        // this thread's 16 cell-ordered slots
    const int gbase = b * NN;

    float dmin[16];
    unsigned pidpk[8];                // 16 pids packed 2-per-u32
    float minx = 1e30f, maxx = -1e30f;
    float miny = 1e30f, maxy = -1e30f;
    float minz = 1e30f, maxz = -1e30f;
    #pragma unroll
    for (int h = 0; h < 8; h++) pidpk[h] = 0u;
    #pragma unroll
    for (int i = 0; i < 16; i++) {
        float4 q = __ldg(&g_pts[gbase + base + i]);
        sxy[base + i] = make_float2(q.x, q.y);
        sz[base + i]  = q.z;
        int pid = __float_as_int(q.w);
        pidpk[i >> 1] |= ((unsigned)pid) << (16 * (i & 1));
        minx = fminf(minx, q.x); maxx = fmaxf(maxx, q.x);
        miny = fminf(miny, q.y); maxy = fmaxf(maxy, q.y);
        minz = fminf(minz, q.z); maxz = fmaxf(maxz, q.z);
        dmin[i] = 1e10f;
        if (pid == 0) *sslot0 = base + i;
    }
    // initial chunk key (dmin all 1e10 -> min pid in chunk wins tiebreak)
    unsigned long long key = 0ull;
    #pragma unroll
    for (int i = 0; i < 16; i++) {
        unsigned pid = (pidpk[i >> 1] >> (16 * (i & 1))) & 0xFFFFu;
        unsigned long long kk = ((unsigned long long)__float_as_uint(1e10f) << 24)
                              | ((unsigned long long)(0x3FFFu - pid) << 10) | (unsigned)i;
        key = kk > key ? kk : key;
    }
    if (tid == 0) g_sidx[b*SS] = 0;
    __syncthreads();
    int slot0 = *sslot0;
    float lx = sxy[slot0].x, ly = sxy[slot0].y, lz = sz[slot0];

    int par = 0;
    for (int t = 1; t < SS; t++) {
        // ---- prune vs chunk AABB ----
        float gmax = __uint_as_float((unsigned)(key >> 24));
        float ex = fmaxf(fmaxf(minx - lx, lx - maxx), 0.0f);
        float ey = fmaxf(fmaxf(miny - ly, ly - maxy), 0.0f);
        float ez = fmaxf(fmaxf(minz - lz, lz - maxz), 0.0f);
        float lb2 = fmaf(ez, ez, fmaf(ey, ey, ex*ex));
        if (lb2 * 0.9998f < gmax) {          // conservative: never wrongly skip
            #pragma unroll
            for (int i = 0; i < 16; i++) {
                float2 xy = sxy[base + i];
                float zz  = sz[base + i];
                float dx = xy.x - lx, dy = xy.y - ly, dz = zz - lz;
                float d  = fmaf(dz, dz, fmaf(dy, dy, dx*dx));
                dmin[i] = fminf(dmin[i], d);
            }
            unsigned long long bk = 0ull;
            #pragma unroll
            for (int i = 0; i < 16; i++) {
                unsigned pid = (pidpk[i >> 1] >> (16 * (i & 1))) & 0xFFFFu;
                unsigned long long kk = ((unsigned long long)__float_as_uint(dmin[i]) << 24)
                                      | ((unsigned long long)(0x3FFFu - pid) << 10) | (unsigned)i;
                bk = kk > bk ? kk : bk;
            }
            key = bk;
        }

        // ---- warp argmax via REDUX: max dminbits, then max invpid among matches ----
        unsigned bd = (unsigned)(key >> 24);
        unsigned mb = __reduce_max_sync(0xffffffffu, bd);
        unsigned cand = (bd == mb) ? (unsigned)(key & 0xFFFFFFu) : 0u;  // invpid<<10|i
        unsigned mc = __reduce_max_sync(0xffffffffu, cand);
        if (bd == mb && cand == mc) {        // unique winner lane (pids unique)
            int i = (int)(key & 0x3FFu);
            swd[par*32 + wid] = mb;
            swq[par*32 + wid] = ((mc >> 10) << 14) | (unsigned)(base + i);
        }
        __syncthreads();

        // ---- every warp reduces the 32 warp-bests (no second barrier) ----
        unsigned dv = swd[par*32 + lane];
        unsigned qv = swq[par*32 + lane];
        unsigned m2 = __reduce_max_sync(0xffffffffu, dv);
        unsigned c2 = (dv == m2) ? qv : 0u;  // invpid<<14|slot, invpid-major
        unsigned w2 = __reduce_max_sync(0xffffffffu, c2);
        int slot = (int)(w2 & 0x3FFFu);
        float2 xy = sxy[slot];
        lx = xy.x; ly = xy.y; lz = sz[slot];
        if (tid == 0) g_sidx[b*SS + t] = 0x3FFF - (int)(w2 >> 14);
        par ^= 1;
    }
}

// ---------------- centers + batch outputs ----------------
__global__ void centers_kernel(float* out_c, float* out_b) {
    int i = blockIdx.x * blockDim.x + threadIdx.x;
    if (i >= MTOT) return;
    int b = i >> 12;
    int gp = b*NN + g_sidx[i];
    float cx = g_posx[gp], cy = g_posy[gp], cz = g_posz[gp];
    g_cx[i] = cx; g_cy[i] = cy; g_cz[i] = cz;
    if (out_c) { out_c[3*i+0] = cx; out_c[3*i+1] = cy; out_c[3*i+2] = cz; }
    if (out_b) { out_b[i] = (float)b; }
}

// ---------------- xw precompute: x @ W1[:16] + b1 ----------------
__global__ void xw_kernel(const float* __restrict__ x,
                          const float* __restrict__ W1,
                          const float* __restrict__ b1) {
    int gid = blockIdx.x * blockDim.x + threadIdx.x;
    if (gid >= BN * 16) return;
    int j  = gid >> 4;
    int c4 = (gid & 15) * 4;
    float a0 = b1[c4+0], a1 = b1[c4+1], a2 = b1[c4+2], a3 = b1[c4+3];
    const float* xr = x + j * FIN;
    #pragma unroll
    for (int k = 0; k < FIN; k++) {
        float xv = xr[k];
        const float* w = W1 + k*64 + c4;
        a0 = fmaf(xv, w[0], a0);
        a1 = fmaf(xv, w[1], a1);
        a2 = fmaf(xv, w[2], a2);
        a3 = fmaf(xv, w[3], a3);
    }
    float4* dst = (float4*)(g_xw + j*64 + c4);
    *dst = make_float4(a0, a1, a2, a3);
}

// ---------------- ball query: warp per center, grid cells, K smallest indices ----------------
__global__ void __launch_bounds__(256) ballq_kernel() {
    __shared__ int cand[8][256];
    __shared__ int scnt_s[8];
    int wid = threadIdx.x >> 5, lane = threadIdx.x & 31;
    int i = blockIdx.x * 8 + wid;
    int b = i >> 12, s = i & 4095;
    float cx = g_cx[i], cy = g_cy[i], cz = g_cz[i];
    if (lane == 0) scnt_s[wid] = 0;
    __syncwarp();

    int icx = (int)(cx * 10.0f); icx = icx < 0 ? 0 : (icx > 9 ? 9 : icx);
    int icy = (int)(cy * 10.0f); icy = icy < 0 ? 0 : (icy > 9 ? 9 : icy);
    int icz = (int)(cz * 10.0f); icz = icz < 0 ? 0 : (icz > 9 ? 9 : icz);
    int zlo = icz > 0 ? icz-1 : 0, zhi = icz < 9 ? icz+1 : 9;
    int ylo = icy > 0 ? icy-1 : 0, yhi = icy < 9 ? icy+1 : 9;
    int xlo = icx > 0 ? icx-1 : 0, xhi = icx < 9 ? icx+1 : 9;

    for (int zz = zlo; zz <= zhi; zz++)
    for (int yy = ylo; yy <= yhi; yy++)
    for (int xx = xlo; xx <= xhi; xx++) {
        int cid = b*NCELL + (zz*10 + yy)*10 + xx;
        int st = g_cellStart[cid];
        int en = st + g_cellCnt[cid];
        for (int idx = st + lane; idx < en; idx += 32) {
            float dx = g_opx[idx] - cx, dy = g_opy[idx] - cy, dz = g_opz[idx] - cz;
            float d2 = fmaf(dz, dz, fmaf(dy, dy, dx*dx));
            int pid = g_opid[idx];
            bool ok = (d2 <= R2) && !(b == 0 && pid == s);  // PyG remove_self_loops
            if (ok) {
                int p = atomicAdd(&scnt_s[wid], 1);
                if (p < 256) cand[wid][p] = pid;
            }
        }
    }
    __syncwarp();
    int m = scnt_s[wid]; if (m > 256) m = 256;
    int take = m < KK ? m : KK;
    // extract 'take' smallest indices (index order = reference sort order)
    for (int r = 0; r < take; r++) {
        int bestkey = 0x7FFFFFFF;
        for (int j = lane; j < m; j += 32) {
            int v = cand[wid][j];          // removed entries hold 0x7FFF (> any pid)
            int key = (v << 8) | j;
            bestkey = min(bestkey, key);
        }
        #pragma unroll
        for (int o = 16; o; o >>= 1)
            bestkey = min(bestkey, __shfl_down_sync(0xffffffffu, bestkey, o));
        bestkey = __shfl_sync(0xffffffffu, bestkey, 0);
        if (lane == 0) {
            g_nbr[i*KK + r] = bestkey >> 8;
            cand[wid][bestkey & 255] = 0x7FFF;
        }
        __syncwarp();
    }
    if (lane == 0) g_cnt[i] = take;
}

// ---------------- fused MLP + max-pool: warp per center ----------------
#define MLP_SMEM ((4096 + 8192 + 192 + 64 + 128) * 4)

__global__ void __launch_bounds__(256) mlp_kernel(const float* __restrict__ W1,
                                                  const float* __restrict__ W2,
                                                  const float* __restrict__ b2,
                                                  const float* __restrict__ W3,
                                                  const float* __restrict__ b3,
                                                  float* __restrict__ out_x) {
    extern __shared__ float sm[];
    float* W2s  = sm;            // 64x64
    float* W3s  = W2s + 4096;    // 64x128
    float* W1rs = W3s + 8192;    // rows 16..18 of W1 (rel weights), 3x64
    float* b2s  = W1rs + 192;
    float* b3s  = b2s + 64;
    int tid = threadIdx.x;
    for (int k = tid; k < 4096; k += 256) W2s[k] = W2[k];
    for (int k = tid; k < 8192; k += 256) W3s[k] = W3[k];
    if (tid < 192) W1rs[tid] = W1[FIN*64 + tid];
    if (tid < 64)  b2s[tid] = b2[tid];
    if (tid < 128) b3s[tid] = b3[tid];
    __syncthreads();

    int wid = tid >> 5, lane = tid & 31;
    int i = blockIdx.x * 8 + wid;
    int b = i >> 12;
    int cnt = g_cnt[i];
    float cx = g_cx[i], cy = g_cy[i], cz = g_cz[i];

    float2 w1x = ((const float2*)(W1rs +   0))[lane];
    float2 w1y = ((const float2*)(W1rs +  64))[lane];
    float2 w1z = ((const float2*)(W1rs + 128))[lane];
    float2 bb2 = ((const float2*)b2s)[lane];
    float4 bb3 = ((const float4*)b3s)[lane];

    float m0 = -1e30f, m1 = -1e30f, m2 = -1e30f, m3 = -1e30f;

    for (int e = 0; e <= cnt; e++) {
        // e == cnt -> PyG add_self_loops edge: src flat index == global dst id == i
        int j = (e < cnt) ? (b*NN + g_nbr[i*KK + e]) : i;
        float rx = g_posx[j] - cx, ry = g_posy[j] - cy, rz = g_posz[j] - cz;
        float2 xw = ((const float2*)(g_xw + j*64))[lane];
        float h1a = fmaf(rz, w1z.x, fmaf(ry, w1y.x, fmaf(rx, w1x.x, xw.x)));
        float h1b = fmaf(rz, w1z.y, fmaf(ry, w1y.y, fmaf(rx, w1x.y, xw.y)));
        h1a = fmaxf(h1a, 0.0f);
        h1b = fmaxf(h1b, 0.0f);

        float a0 = bb2.x, a1 = bb2.y;
        #pragma unroll 8
        for (int k0 = 0; k0 < 32; k0++) {
            float va = __shfl_sync(0xffffffffu, h1a, k0);   // h1[2*k0]
            float vb = __shfl_sync(0xffffffffu, h1b, k0);   // h1[2*k0+1]
            float2 wa = ((const float2*)(W2s + (2*k0  )*64))[lane];
            float2 wb = ((const float2*)(W2s + (2*k0+1)*64))[lane];
            a0 = fmaf(va, wa.x, a0); a0 = fmaf(vb, wb.x, a0);
            a1 = fmaf(va, wa.y, a1); a1 = fmaf(vb, wb.y, a1);
        }
        float h2a = fmaxf(a0, 0.0f), h2b = fmaxf(a1, 0.0f);

        float c0 = bb3.x, c1 = bb3.y, c2 = bb3.z, c3 = bb3.w;
        #pragma unroll 8
        for (int k0 = 0; k0 < 32; k0++) {
            float va = __shfl_sync(0xffffffffu, h2a, k0);   // h2[2*k0]
            float vb = __shfl_sync(0xffffffffu, h2b, k0);   // h2[2*k0+1]
            float4 wa = ((const float4*)(W3s + (2*k0  )*128))[lane];
            float4 wb = ((const float4*)(W3s + (2*k0+1)*128))[lane];
            c0 = fmaf(va, wa.x, c0); c0 = fmaf(vb, wb.x, c0);
            c1 = fmaf(va, wa.y, c1); c1 = fmaf(vb, wb.y, c1);
            c2 = fmaf(va, wa.z, c2); c2 = fmaf(vb, wb.z, c2);
            c3 = fmaf(va, wa.w, c3); c3 = fmaf(vb, wb.w, c3);
        }
        m0 = fmaxf(m0, c0); m1 = fmaxf(m1, c1);
        m2 = fmaxf(m2, c2); m3 = fmaxf(m3, c3);
    }
    ((float4*)(out_x + i*128))[lane] = make_float4(m0, m1, m2, m3);
}

// ---------------- host launcher ----------------
extern "C" void kernel_launch(void* const* d_in, const int* in_sizes, int n_in,
                              void* d_out, int out_size) {
    const float* x   = (const float*)d_in[0];
    const float* pos = (const float*)d_in[1];
    // d_in[2] = batch (int32) -- derivable, unused
    const float* W1  = (const float*)d_in[3];
    const float* b1  = (const float*)d_in[4];
    const float* W2  = (const float*)d_in[5];
    const float* b2  = (const float*)d_in[6];
    const float* W3  = (const float*)d_in[7];
    const float* b3  = (const float*)d_in[8];

    float* out   = (float*)d_out;
    float* out_c = (out_size >= MTOT*131) ? out + MTOT*128 : nullptr;
    float* out_b = (out_size >= MTOT*132) ? out + MTOT*131 : nullptr;

    cudaFuncSetAttribute(fps_chunk_kernel, cudaFuncAttributeMaxDynamicSharedMemorySize, FPS6_SMEM);
    cudaFuncSetAttribute(mlp_kernel, cudaFuncAttributeMaxDynamicSharedMemorySize, MLP_SMEM);

    prep_kernel     <<<(BN + 255)/256, 256>>>(pos);
    count_kernel    <<<(BN + 255)/256, 256>>>();
    scan_kernel     <<<1, 32>>>();
    scatter_kernel  <<<(BN + 255)/256, 256>>>();
    gather_kernel   <<<(BN + 255)/256, 256>>>();
    xw_kernel       <<<(BN*16 + 127)/128, 128>>>(x, W1, b1);
    fps_chunk_kernel<<<BB, 1024, FPS6_SMEM>>>();
    centers_kernel  <<<(MTOT + 255)/256, 256>>>(out_c, out_b);
    ballq_kernel    <<<MTOT/8, 256>>>();
    mlp_kernel      <<<MTOT/8, 256, MLP_SMEM>>>(W1, W2, b2, W3, b3, out);
}

// round 12
// speedup vs baseline: 1.2342x; 1.2342x over previous
#include <cuda_runtime.h>
#include <cstdint>

#define BB   2
#define NN   16384
#define SS   4096
#define KK   32
#define FIN  16
#define MTOT (BB*SS)      /* 8192 centers */
#define BN   (BB*NN)      /* 32768 points */
#define NCELL 1000        /* 10x10x10 cells of size R=0.1 per cloud */
#define R2   0.01f

// ---------------- device scratch (no runtime allocation allowed) ----------------
__device__ float  g_posx[BN], g_posy[BN], g_posz[BN];
__device__ int    g_sidx[MTOT];                 // selected local point idx per (b,s)
__device__ float  g_cx[MTOT], g_cy[MTOT], g_cz[MTOT];
__device__ int    g_cellCnt[BB*NCELL];
__device__ int    g_cellStart[BB*NCELL];
__device__ int    g_cellCur[BB*NCELL];
__device__ int    g_cellPts[BN];
__device__ float  g_opx[BN], g_opy[BN], g_opz[BN];  // cell-ordered positions
__device__ int    g_opid[BN];                        // cell-ordered -> local point id
__device__ int2   g_ozp[BN];                         // fused {z bits, local pid}
__device__ float4 g_pts[BN];                         // fused {x, y, z, bits(pid)}
__device__ float  g_xw[BN*64];                  // x @ W1[:16] + b1   (8 MB)
__device__ int    g_nbr[MTOT*KK];
__device__ int    g_cnt[MTOT];

// ---------------- prep: SoA split of pos + zero cell counts ----------------
__global__ void prep_kernel(const float* __restrict__ pos) {
    int i = blockIdx.x * blockDim.x + threadIdx.x;
    if (i < BN) {
        g_posx[i] = pos[3*i+0];
        g_posy[i] = pos[3*i+1];
        g_posz[i] = pos[3*i+2];
    }
    if (i < BB*NCELL) g_cellCnt[i] = 0;
}

__device__ __forceinline__ int cell_of(float px, float py, float pz, int b) {
    int cx = (int)(px * 10.0f); cx = cx < 0 ? 0 : (cx > 9 ? 9 : cx);
    int cy = (int)(py * 10.0f); cy = cy < 0 ? 0 : (cy > 9 ? 9 : cy);
    int cz = (int)(pz * 10.0f); cz = cz < 0 ? 0 : (cz > 9 ? 9 : cz);
    return b * NCELL + (cz * 10 + cy) * 10 + cx;
}

__global__ void count_kernel() {
    int i = blockIdx.x * blockDim.x + threadIdx.x;
    if (i >= BN) return;
    int b = i >> 14;
    atomicAdd(&g_cellCnt[cell_of(g_posx[i], g_posy[i], g_posz[i], b)], 1);
}

// single-warp exclusive scan over 2000 cells
__global__ void scan_kernel() {
    int lane = threadIdx.x;
    int acc = 0;
    for (int base = 0; base < BB*NCELL; base += 32) {
        int idx = base + lane;
        int v = (idx < BB*NCELL) ? g_cellCnt[idx] : 0;
        int inc = v;
        #pragma unroll
        for (int o = 1; o < 32; o <<= 1) {
            int n = __shfl_up_sync(0xffffffffu, inc, o);
            if (lane >= o) inc += n;
        }
        if (idx < BB*NCELL) {
            g_cellStart[idx] = acc + inc - v;
            g_cellCur[idx]   = acc + inc - v;
        }
        acc += __shfl_sync(0xffffffffu, inc, 31);
    }
}

__global__ void scatter_kernel() {
    int i = blockIdx.x * blockDim.x + threadIdx.x;
    if (i >= BN) return;
    int b = i >> 14;
    int cid = cell_of(g_posx[i], g_posy[i], g_posz[i], b);
    int slot = atomicAdd(&g_cellCur[cid], 1);
    g_cellPts[slot] = i & (NN - 1);   // local index within cloud
}

// build cell-ordered arrays: SoA pos (ballq), fused (FPS), id map
__global__ void gather_kernel() {
    int i = blockIdx.x * blockDim.x + threadIdx.x;
    if (i >= BN) return;
    int b = i >> 14;                 // slots of cloud b occupy [b*NN, (b+1)*NN)
    int pid = g_cellPts[i];
    int gp = b*NN + pid;
    float px = g_posx[gp], py = g_posy[gp], pz = g_posz[gp];
    g_opx[i] = px;
    g_opy[i] = py;
    g_opz[i] = pz;
    g_opid[i] = pid;
    g_ozp[i] = make_int2(__float_as_int(pz), pid);
    g_pts[i] = make_float4(px, py, pz, __int_as_float(pid));
}

// ---------------- grid-pruned FPS: lane-owns-cell, slot-carrying REDUX, 1 barrier ----
// ordering: (dmin desc, pid asc). dmin>=0 -> float bits u32-monotone.
// combo q = (0x3FFF - pid) << 14 | slot   (28 bits; pid unique -> q unique)
#define FPS7_SMEM (NN*8 + NN*4 + 64*4*3 + 32)

__global__ void __launch_bounds__(1024, 1) fps_lane_kernel() {
    extern __shared__ float sm[];
    float2*   sxy = (float2*)sm;                  // NN  (x,y)
    float*    sdmin = (float*)(sxy + NN);         // NN
    unsigned* swd = (unsigned*)(sdmin + NN);      // 2 x 32 warp best dmin bits
    unsigned* swq = swd + 64;                     // 2 x 32 warp best combo
    float*    swz = (float*)(swq + 64);           // 2 x 32 warp best z

    const int b    = blockIdx.x;
    const int tid  = threadIdx.x;
    const int lane = tid & 31;
    const int wid  = tid >> 5;
    const int gbase = b * NN;

    for (int i = tid; i < NN; i += 1024) {
        float4 q = __ldg(&g_pts[gbase + i]);
        sxy[i] = make_float2(q.x, q.y);
        sdmin[i] = 1e10f;
    }

    // lane-owned cell: c = (lane<<5) | wid  (spreads 3x3x3 neighborhoods across warps)
    const int mycell = (lane << 5) | wid;
    const bool valid = (mycell < NCELL);
    int cellStart = 0, cellCnt = 0;
    float cx0 = 0.f, cx1 = 0.f, cy0 = 0.f, cy1 = 0.f, cz0 = 0.f, cz1 = 0.f;
    unsigned cellD = 0u, cellQ = 0u;              // per-cell persistent best
    float cellZ = 0.f;
    if (valid) {
        cellCnt   = g_cellCnt[b*NCELL + mycell];
        cellStart = g_cellStart[b*NCELL + mycell] - gbase;
        int cz = mycell / 100;
        int r  = mycell - cz * 100;
        int cy = r / 10;
        int cxi = r - cy * 10;
        cx0 = (float)cxi * 0.1f; cx1 = (float)(cxi+1) * 0.1f;
        cy0 = (float)cy  * 0.1f; cy1 = (float)(cy +1) * 0.1f;
        cz0 = (float)cz  * 0.1f; cz1 = (float)(cz +1) * 0.1f;
        if (cellCnt) cellD = __float_as_uint(1e10f);   // all cells touched at t=1
    }
    if (tid == 0) g_sidx[b*SS] = 0;
    // first center: original point 0 (broadcast L2 loads, off the loop)
    float lx = g_posx[gbase], ly = g_posy[gbase], lz = g_posz[gbase];
    __syncthreads();

    int par = 0;
    for (int t = 1; t < SS; t++) {
        // ---- prune: one lane per owned cell (pure ALU) ----
        bool need = false;
        if (valid && cellCnt) {
            float ex = fmaxf(fmaxf(cx0 - lx, lx - cx1), 0.0f);
            float ey = fmaxf(fmaxf(cy0 - ly, ly - cy1), 0.0f);
            float ez = fmaxf(fmaxf(cz0 - lz, lz - cz1), 0.0f);
            float lb2 = fmaf(ez, ez, fmaf(ey, ey, ex*ex));
            need = (lb2 * 0.9998f < __uint_as_float(cellD));   // never wrongly skip
        }
        unsigned mask = __ballot_sync(0xffffffffu, need);

        // ---- process touched cells, software-pipelined z/pid loads ----
        int src = -1, st = 0, cn = 0;
        int2 zp = make_int2(0, 0);
        if (mask) {
            src = __ffs(mask) - 1; mask &= mask - 1;
            st = __shfl_sync(0xffffffffu, cellStart, src);
            cn = __shfl_sync(0xffffffffu, cellCnt,   src);
            if (lane < cn) zp = __ldg(&g_ozp[gbase + st + lane]);
        }
        while (src >= 0) {
            // prefetch next touched cell
            int nsrc = -1, nst = 0, ncn = 0;
            int2 nzp = make_int2(0, 0);
            if (mask) {
                nsrc = __ffs(mask) - 1; mask &= mask - 1;
                nst = __shfl_sync(0xffffffffu, cellStart, nsrc);
                ncn = __shfl_sync(0xffffffffu, cellCnt,   nsrc);
                if (lane < ncn) nzp = __ldg(&g_ozp[gbase + nst + lane]);
            }
            // per-lane update + best over this cell's points
            unsigned bd = 0u, bq = 0u;
            float bz = 0.f;
            if (lane < cn) {
                int s = st + lane;
                float2 xy = sxy[s];
                float pz = __int_as_float(zp.x);
                float dx = xy.x - lx, dy = xy.y - ly, dz = pz - lz;
                float d  = fmaf(dz, dz, fmaf(dy, dy, dx*dx));
                float nm = fminf(sdmin[s], d);
                sdmin[s] = nm;
                bd = __float_as_uint(nm);
                bq = ((0x3FFFu - (unsigned)zp.y) << 14) | (unsigned)s;
                bz = pz;
            }
            for (int p = lane + 32; p < cn; p += 32) {   // rare: cells with >32 pts
                int s = st + p;
                int2 zp2 = __ldg(&g_ozp[gbase + s]);
                float2 xy = sxy[s];
                float pz = __int_as_float(zp2.x);
                float dx = xy.x - lx, dy = xy.y - ly, dz = pz - lz;
                float d  = fmaf(dz, dz, fmaf(dy, dy, dx*dx));
                float nm = fminf(sdmin[s], d);
                sdmin[s] = nm;
                unsigned db = __float_as_uint(nm);
                unsigned qb = ((0x3FFFu - (unsigned)zp2.y) << 14) | (unsigned)s;
                if (db > bd || (db == bd && qb > bq)) { bd = db; bq = qb; bz = pz; }
            }
            // cell argmax: max dmin bits, then max combo among matches
            unsigned mb = __reduce_max_sync(0xffffffffu, bd);
            unsigned cand = (bd == mb) ? bq : 0u;
            unsigned mq = __reduce_max_sync(0xffffffffu, cand);
            unsigned wm = __ballot_sync(0xffffffffu, bd == mb && bq == mq);
            int wl = __ffs(wm) - 1;
            float wz = __shfl_sync(0xffffffffu, bz, wl);
            if (lane == src) { cellD = mb; cellQ = mq; cellZ = wz; }
            src = nsrc; st = nst; cn = ncn; zp = nzp;
        }

        // ---- warp best over owned cells: winner lane writes slot directly ----
        unsigned mb2 = __reduce_max_sync(0xffffffffu, cellD);
        unsigned cand2 = (cellD == mb2) ? cellQ : 0u;
        unsigned c2 = __reduce_max_sync(0xffffffffu, cand2);
        if (cellD == mb2 && cellQ == c2) {     // unique (or all-zero: benign dup writes)
            swd[par*32 + wid] = mb2;
            swq[par*32 + wid] = c2;
            swz[par*32 + wid] = cellZ;
        }
        __syncthreads();

        // ---- every warp redundantly reduces the 32 warp-bests (no 2nd barrier) ----
        unsigned dv = swd[par*32 + lane];
        unsigned qv = swq[par*32 + lane];
        unsigned m3 = __reduce_max_sync(0xffffffffu, dv);
        unsigned cand3 = (dv == m3) ? qv : 0u;
        unsigned c3 = __reduce_max_sync(0xffffffffu, cand3);
        unsigned wm3 = __ballot_sync(0xffffffffu, dv == m3 && qv == c3);
        int wl3 = __ffs(wm3) - 1;
        int slot = (int)(c3 & 0x3FFFu);
        float2 xy = sxy[slot];                 // broadcast LDS
        lx = xy.x; ly = xy.y;
        lz = swz[par*32 + wl3];                // broadcast LDS
        if (tid == 0) g_sidx[b*SS + t] = 0x3FFF - (int)(c3 >> 14);
        par ^= 1;
    }
}

// ---------------- centers + batch outputs ----------------
__global__ void centers_kernel(float* out_c, float* out_b) {
    int i = blockIdx.x * blockDim.x + threadIdx.x;
    if (i >= MTOT) return;
    int b = i >> 12;
    int gp = b*NN + g_sidx[i];
    float cx = g_posx[gp], cy = g_posy[gp], cz = g_posz[gp];
    g_cx[i] = cx; g_cy[i] = cy; g_cz[i] = cz;
    if (out_c) { out_c[3*i+0] = cx; out_c[3*i+1] = cy; out_c[3*i+2] = cz; }
    if (out_b) { out_b[i] = (float)b; }
}

// ---------------- xw precompute: x @ W1[:16] + b1 ----------------
__global__ void xw_kernel(const float* __restrict__ x,
                          const float* __restrict__ W1,
                          const float* __restrict__ b1) {
    int gid = blockIdx.x * blockDim.x + threadIdx.x;
    if (gid >= BN * 16) return;
    int j  = gid >> 4;
    int c4 = (gid & 15) * 4;
    float a0 = b1[c4+0], a1 = b1[c4+1], a2 = b1[c4+2], a3 = b1[c4+3];
    const float* xr = x + j * FIN;
    #pragma unroll
    for (int k = 0; k < FIN; k++) {
        float xv = xr[k];
        const float* w = W1 + k*64 + c4;
        a0 = fmaf(xv, w[0], a0);
        a1 = fmaf(xv, w[1], a1);
        a2 = fmaf(xv, w[2], a2);
        a3 = fmaf(xv, w[3], a3);
    }
    float4* dst = (float4*)(g_xw + j*64 + c4);
    *dst = make_float4(a0, a1, a2, a3);
}

// ---------------- ball query: warp per center, grid cells, K smallest indices ----------------
__global__ void __launch_bounds__(256) ballq_kernel() {
    __shared__ int cand[8][256];
    __shared__ int scnt_s[8];
    int wid = threadIdx.x >> 5, lane = threadIdx.x & 31;
    int i = blockIdx.x * 8 + wid;
    int b = i >> 12, s = i & 4095;
    float cx = g_cx[i], cy = g_cy[i], cz = g_cz[i];
    if (lane == 0) scnt_s[wid] = 0;
    __syncwarp();

    int icx = (int)(cx * 10.0f); icx = icx < 0 ? 0 : (icx > 9 ? 9 : icx);
    int icy = (int)(cy * 10.0f); icy = icy < 0 ? 0 : (icy > 9 ? 9 : icy);
    int icz = (int)(cz * 10.0f); icz = icz < 0 ? 0 : (icz > 9 ? 9 : icz);
    int zlo = icz > 0 ? icz-1 : 0, zhi = icz < 9 ? icz+1 : 9;
    int ylo = icy > 0 ? icy-1 : 0, yhi = icy < 9 ? icy+1 : 9;
    int xlo = icx > 0 ? icx-1 : 0, xhi = icx < 9 ? icx+1 : 9;

    for (int zz = zlo; zz <= zhi; zz++)
    for (int yy = ylo; yy <= yhi; yy++)
    for (int xx = xlo; xx <= xhi; xx++) {
        int cid = b*NCELL + (zz*10 + yy)*10 + xx;
        int st = g_cellStart[cid];
        int en = st + g_cellCnt[cid];
        for (int idx = st + lane; idx < en; idx += 32) {
            float dx = g_opx[idx] - cx, dy = g_opy[idx] - cy, dz = g_opz[idx] - cz;
            float d2 = fmaf(dz, dz, fmaf(dy, dy, dx*dx));
            int pid = g_opid[idx];
            bool ok = (d2 <= R2) && !(b == 0 && pid == s);  // PyG remove_self_loops
            if (ok) {
                int p = atomicAdd(&scnt_s[wid], 1);
                if (p < 256) cand[wid][p] = pid;
            }
        }
    }
    __syncwarp();
    int m = scnt_s[wid]; if (m > 256) m = 256;
    int take = m < KK ? m : KK;
    // extract 'take' smallest indices (index order = reference sort order)
    for (int r = 0; r < take; r++) {
        int bestkey = 0x7FFFFFFF;
        for (int j = lane; j < m; j += 32) {
            int v = cand[wid][j];          // removed entries hold 0x7FFF (> any pid)
            int key = (v << 8) | j;
            bestkey = min(bestkey, key);
        }
        #pragma unroll
        for (int o = 16; o; o >>= 1)
            bestkey = min(bestkey, __shfl_down_sync(0xffffffffu, bestkey, o));
        bestkey = __shfl_sync(0xffffffffu, bestkey, 0);
        if (lane == 0) {
            g_nbr[i*KK + r] = bestkey >> 8;
            cand[wid][bestkey & 255] = 0x7FFF;
        }
        __syncwarp();
    }
    if (lane == 0) g_cnt[i] = take;
}

// ---------------- fused MLP + max-pool: warp per center, smem h-buffers ----------------
#define MLP_SMEM ((4096 + 8192 + 192 + 64 + 128 + 8*128) * 4)

__global__ void __launch_bounds__(256) mlp_kernel(const float* __restrict__ W1,
                                                  const float* __restrict__ W2,
                                                  const float* __restrict__ b2,
                                                  const float* __restrict__ W3,
                                                  const float* __restrict__ b3,
                                                  float* __restrict__ out_x) {
    extern __shared__ float sm[];
    float* W2s  = sm;            // 64x64
    float* W3s  = W2s + 4096;    // 64x128
    float* W1rs = W3s + 8192;    // rows 16..18 of W1 (rel weights), 3x64
    float* b2s  = W1rs + 192;
    float* b3s  = b2s + 64;
    float* hbuf = b3s + 128;     // 8 warps x (64 h1 + 64 h2)
    int tid = threadIdx.x;
    for (int k = tid; k < 4096; k += 256) W2s[k] = W2[k];
    for (int k = tid; k < 8192; k += 256) W3s[k] = W3[k];
    if (tid < 192) W1rs[tid] = W1[FIN*64 + tid];
    if (tid < 64)  b2s[tid] = b2[tid];
    if (tid < 128) b3s[tid] = b3[tid];
    __syncthreads();

    int wid = tid >> 5, lane = tid & 31;
    float* bufA = hbuf + wid * 128;       // h1 (64)
    float* bufB = bufA + 64;              // h2 (64)
    int i = blockIdx.x * 8 + wid;
    int b = i >> 12;
    int cnt = g_cnt[i];
    float cx = g_cx[i], cy = g_cy[i], cz = g_cz[i];

    float2 w1x = ((const float2*)(W1rs +   0))[lane];
    float2 w1y = ((const float2*)(W1rs +  64))[lane];
    float2 w1z = ((const float2*)(W1rs + 128))[lane];
    float2 bb2 = ((const float2*)b2s)[lane];
    float4 bb3 = ((const float4*)b3s)[lane];

    float m0 = -1e30f, m1 = -1e30f, m2 = -1e30f, m3 = -1e30f;

    for (int e = 0; e <= cnt; e++) {
        // e == cnt -> PyG add_self_loops edge: src flat index == global dst id == i
        int j = (e < cnt) ? (b*NN + g_nbr[i*KK + e]) : i;
        float rx = g_posx[j] - cx, ry = g_posy[j] - cy, rz = g_posz[j] - cz;
        float2 xw = ((const float2*)(g_xw + j*64))[lane];
        float h1a = fmaf(rz, w1z.x, fmaf(ry, w1y.x, fmaf(rx, w1x.x, xw.x)));
        float h1b = fmaf(rz, w1z.y, fmaf(ry, w1y.y, fmaf(rx, w1x.y, xw.y)));
        h1a = fmaxf(h1a, 0.0f);
        h1b = fmaxf(h1b, 0.0f);
        ((float2*)bufA)[lane] = make_float2(h1a, h1b);   // h1[2*lane], h1[2*lane+1]
        __syncwarp();

        float a0 = bb2.x, a1 = bb2.y;
        #pragma unroll
        for (int k4 = 0; k4 < 16; k4++) {                // k = 4*k4 .. 4*k4+3 ascending
            float4 hv = ((const float4*)bufA)[k4];       // broadcast LDS.128
            float2 w0 = ((const float2*)(W2s + (4*k4+0)*64))[lane];
            float2 w1 = ((const float2*)(W2s + (4*k4+1)*64))[lane];
            float2 w2 = ((const float2*)(W2s + (4*k4+2)*64))[lane];
            float2 w3 = ((const float2*)(W2s + (4*k4+3)*64))[lane];
            a0 = fmaf(hv.x, w0.x, a0); a1 = fmaf(hv.x, w0.y, a1);
            a0 = fmaf(hv.y, w1.x, a0); a1 = fmaf(hv.y, w1.y, a1);
            a0 = fmaf(hv.z, w2.x, a0); a1 = fmaf(hv.z, w2.y, a1);
            a0 = fmaf(hv.w, w3.x, a0); a1 = fmaf(hv.w, w3.y, a1);
        }
        float h2a = fmaxf(a0, 0.0f), h2b = fmaxf(a1, 0.0f);
        ((float2*)bufB)[lane] = make_float2(h2a, h2b);
        __syncwarp();

        float c0 = bb3.x, c1 = bb3.y, c2 = bb3.z, c3 = bb3.w;
        #pragma unroll
        for (int k4 = 0; k4 < 16; k4++) {
            float4 hv = ((const float4*)bufB)[k4];
            float4 v0 = ((const float4*)(W3s + (4*k4+0)*128))[lane];
            float4 v1 = ((const float4*)(W3s + (4*k4+1)*128))[lane];
            float4 v2 = ((const float4*)(W3s + (4*k4+2)*128))[lane];
            float4 v3 = ((const float4*)(W3s + (4*k4+3)*128))[lane];
            c0 = fmaf(hv.x, v0.x, c0); c1 = fmaf(hv.x, v0.y, c1);
            c2 = fmaf(hv.x, v0.z, c2); c3 = fmaf(hv.x, v0.w, c3);
            c0 = fmaf(hv.y, v1.x, c0); c1 = fmaf(hv.y, v1.y, c1);
            c2 = fmaf(hv.y, v1.z, c2); c3 = fmaf(hv.y, v1.w, c3);
            c0 = fmaf(hv.z, v2.x, c0); c1 = fmaf(hv.z, v2.y, c1);
            c2 = fmaf(hv.z, v2.z, c2); c3 = fmaf(hv.z, v2.w, c3);
            c0 = fmaf(hv.w, v3.x, c0); c1 = fmaf(hv.w, v3.y, c1);
            c2 = fmaf(hv.w, v3.z, c2); c3 = fmaf(hv.w, v3.w, c3);
        }
        m0 = fmaxf(m0, c0); m1 = fmaxf(m1, c1);
        m2 = fmaxf(m2, c2); m3 = fmaxf(m3, c3);
    }
    ((float4*)(out_x + i*128))[lane] = make_float4(m0, m1, m2, m3);
}

// ---------------- host launcher ----------------
extern "C" void kernel_launch(void* const* d_in, const int* in_sizes, int n_in,
                              void* d_out, int out_size) {
    const float* x   = (const float*)d_in[0];
    const float* pos = (const float*)d_in[1];
    // d_in[2] = batch (int32) -- derivable, unused
    const float* W1  = (const float*)d_in[3];
    const float* b1  = (const float*)d_in[4];
    const float* W2  = (const float*)d_in[5];
    const float* b2  = (const float*)d_in[6];
    const float* W3  = (const float*)d_in[7];
    const float* b3  = (const float*)d_in[8];

    float* out   = (float*)d_out;
    float* out_c = (out_size >= MTOT*131) ? out + MTOT*128 : nullptr;
    float* out_b = (out_size >= MTOT*132) ? out + MTOT*131 : nullptr;

    cudaFuncSetAttribute(fps_lane_kernel, cudaFuncAttributeMaxDynamicSharedMemorySize, FPS7_SMEM);
    cudaFuncSetAttribute(mlp_kernel, cudaFuncAttributeMaxDynamicSharedMemorySize, MLP_SMEM);

    prep_kernel    <<<(BN + 255)/256, 256>>>(pos);
    count_kernel   <<<(BN + 255)/256, 256>>>();
    scan_kernel    <<<1, 32>>>();
    scatter_kernel <<<(BN + 255)/256, 256>>>();
    gather_kernel  <<<(BN + 255)/256, 256>>>();
    xw_kernel      <<<(BN*16 + 127)/128, 128>>>(x, W1, b1);
    fps_lane_kernel<<<BB, 1024, FPS7_SMEM>>>();
    centers_kernel <<<(MTOT + 255)/256, 256>>>(out_c, out_b);
    ballq_kernel   <<<MTOT/8, 256>>>();
    mlp_kernel     <<<MTOT/8, 256, MLP_SMEM>>>(W1, W2, b2, W3, b3, out);
}

// round 14
// speedup vs baseline: 1.3244x; 1.0731x over previous
#include <cuda_runtime.h>
#include <cstdint>

#define BB   2
#define NN   16384
#define SS   4096
#define KK   32
#define FIN  16
#define MTOT (BB*SS)      /* 8192 centers */
#define BN   (BB*NN)      /* 32768 points */
#define NCELL 1000        /* 10x10x10 cells of size R=0.1 per cloud */
#define R2   0.01f

// ---------------- device scratch (no runtime allocation allowed) ----------------
__device__ float  g_posx[BN], g_posy[BN], g_posz[BN];
__device__ int    g_sidx[MTOT];                 // selected local point idx per (b,s)
__device__ float  g_cx[MTOT], g_cy[MTOT], g_cz[MTOT];
__device__ int    g_cellCnt[BB*NCELL];
__device__ int    g_cellStart[BB*NCELL];
__device__ int    g_cellCur[BB*NCELL];
__device__ int    g_cellPts[BN];
__device__ float  g_opx[BN], g_opy[BN], g_opz[BN];  // cell-ordered positions
__device__ int    g_opid[BN];                        // cell-ordered -> local point id
__device__ int2   g_ozp[BN];                         // fused {z bits, local pid}
__device__ float4 g_pts[BN];                         // fused {x, y, z, bits(pid)}
__device__ float  g_xw[BN*64];                  // x @ W1[:16] + b1   (8 MB)
__device__ int    g_nbr[MTOT*KK];
__device__ int    g_cnt[MTOT];

// ---------------- prep: SoA split of pos + zero cell counts ----------------
__global__ void prep_kernel(const float* __restrict__ pos) {
    int i = blockIdx.x * blockDim.x + threadIdx.x;
    if (i < BN) {
        g_posx[i] = pos[3*i+0];
        g_posy[i] = pos[3*i+1];
        g_posz[i] = pos[3*i+2];
    }
    if (i < BB*NCELL) g_cellCnt[i] = 0;
}

__device__ __forceinline__ int cell_of(float px, float py, float pz, int b) {
    int cx = (int)(px * 10.0f); cx = cx < 0 ? 0 : (cx > 9 ? 9 : cx);
    int cy = (int)(py * 10.0f); cy = cy < 0 ? 0 : (cy > 9 ? 9 : cy);
    int cz = (int)(pz * 10.0f); cz = cz < 0 ? 0 : (cz > 9 ? 9 : cz);
    return b * NCELL + (cz * 10 + cy) * 10 + cx;
}

__global__ void count_kernel() {
    int i = blockIdx.x * blockDim.x + threadIdx.x;
    if (i >= BN) return;
    int b = i >> 14;
    atomicAdd(&g_cellCnt[cell_of(g_posx[i], g_posy[i], g_posz[i], b)], 1);
}

// single-warp exclusive scan over 2000 cells
__global__ void scan_kernel() {
    int lane = threadIdx.x;
    int acc = 0;
    for (int base = 0; base < BB*NCELL; base += 32) {
        int idx = base + lane;
        int v = (idx < BB*NCELL) ? g_cellCnt[idx] : 0;
        int inc = v;
        #pragma unroll
        for (int o = 1; o < 32; o <<= 1) {
            int n = __shfl_up_sync(0xffffffffu, inc, o);
            if (lane >= o) inc += n;
        }
        if (idx < BB*NCELL) {
            g_cellStart[idx] = acc + inc - v;
            g_cellCur[idx]   = acc + inc - v;
        }
        acc += __shfl_sync(0xffffffffu, inc, 31);
    }
}

__global__ void scatter_kernel() {
    int i = blockIdx.x * blockDim.x + threadIdx.x;
    if (i >= BN) return;
    int b = i >> 14;
    int cid = cell_of(g_posx[i], g_posy[i], g_posz[i], b);
    int slot = atomicAdd(&g_cellCur[cid], 1);
    g_cellPts[slot] = i & (NN - 1);   // local index within cloud
}

// build cell-ordered arrays: SoA pos (ballq), fused (FPS), id map
__global__ void gather_kernel() {
    int i = blockIdx.x * blockDim.x + threadIdx.x;
    if (i >= BN) return;
    int b = i >> 14;                 // slots of cloud b occupy [b*NN, (b+1)*NN)
    int pid = g_cellPts[i];
    int gp = b*NN + pid;
    float px = g_posx[gp], py = g_posy[gp], pz = g_posz[gp];
    g_opx[i] = px;
    g_opy[i] = py;
    g_opz[i] = pz;
    g_opid[i] = pid;
    g_ozp[i] = make_int2(__float_as_int(pz), pid);
    g_pts[i] = make_float4(px, py, pz, __int_as_float(pid));
}

// ---------------- grid-pruned FPS with exact top-2 batched selection ----------------
// ordering key: (dmin desc, pid asc); dmin>=0 -> float bits u32-monotone.
// combo q = (0x3FFF - pid) << 14 | slot   (unique via pid)
#define FPS8_SMEM (NN*8 + NN*4 + 64*6*4 + 64)

__global__ void __launch_bounds__(1024, 1) fps_top2_kernel() {
    extern __shared__ float sm[];
    float2*   sxy   = (float2*)sm;                // NN (x,y)
    float*    sdmin = (float*)(sxy + NN);         // NN
    unsigned* s1d   = (unsigned*)(sdmin + NN);    // 2x32 record1 dmin bits
    unsigned* s1q   = s1d + 64;                   // 2x32 record1 combo
    float*    s1z   = (float*)(s1q + 64);         // 2x32 record1 z
    unsigned* s2d   = (unsigned*)(s1z + 64);      // 2x32 record2 dmin bits
    unsigned* s2q   = s2d + 64;                   // 2x32 record2 combo
    float*    s2z   = (float*)(s2q + 64);         // 2x32 record2 z

    const int b    = blockIdx.x;
    const int tid  = threadIdx.x;
    const int lane = tid & 31;
    const int wid  = tid >> 5;
    const int gbase = b * NN;

    for (int i = tid; i < NN; i += 1024) {
        float4 q = __ldg(&g_pts[gbase + i]);
        sxy[i] = make_float2(q.x, q.y);
        sdmin[i] = 1e10f;
    }

    // lane-owned cell: c = (lane<<5) | wid
    const int mycell = (lane << 5) | wid;
    const bool valid = (mycell < NCELL);
    int cellStart = 0, cellCnt = 0;
    float ccx = 0.f, ccy = 0.f, ccz = 0.f;        // cell centers (half-size 0.05)
    unsigned cD1 = 0u, cQ1 = 0u, cD2 = 0u, cQ2 = 0u;
    float cZ1 = 0.f, cZ2 = 0.f;
    if (valid) {
        cellCnt   = g_cellCnt[b*NCELL + mycell];
        cellStart = g_cellStart[b*NCELL + mycell] - gbase;
        int cz = mycell / 100;
        int r  = mycell - cz * 100;
        int cy = r / 10;
        int cxi = r - cy * 10;
        ccx = (float)cxi * 0.1f + 0.05f;
        ccy = (float)cy  * 0.1f + 0.05f;
        ccz = (float)cz  * 0.1f + 0.05f;
        if (cellCnt) cD1 = __float_as_uint(1e10f);   // all cells touched at sweep 1
    }
    if (tid == 0) g_sidx[b*SS] = 0;
    float ax = g_posx[gbase], ay = g_posy[gbase], az = g_posz[gbase];
    float bx = ax, by = ay, bz = az;              // update pair (A, B); initially both = pt0
    __syncthreads();

    int par = 0;
    int t = 1;
    while (t < SS) {
        // ---- prune vs both update points (conservative margin) ----
        bool need = false;
        if (valid && cellCnt) {
            float exa = fmaxf(fabsf(ccx - ax) - 0.05f, 0.f);
            float eya = fmaxf(fabsf(ccy - ay) - 0.05f, 0.f);
            float eza = fmaxf(fabsf(ccz - az) - 0.05f, 0.f);
            float la  = fmaf(eza, eza, fmaf(eya, eya, exa*exa));
            float exb = fmaxf(fabsf(ccx - bx) - 0.05f, 0.f);
            float eyb = fmaxf(fabsf(ccy - by) - 0.05f, 0.f);
            float ezb = fmaxf(fabsf(ccz - bz) - 0.05f, 0.f);
            float lb  = fmaf(ezb, ezb, fmaf(eyb, eyb, exb*exb));
            need = (fminf(la, lb) * 0.9998f < __uint_as_float(cD1));
        }
        unsigned mask = __ballot_sync(0xffffffffu, need);

        // ---- process touched cells (pipelined z/pid loads), fresh per-cell top-2 ----
        int src = -1, st = 0, cn = 0;
        int2 zp = make_int2(0, 0);
        if (mask) {
            src = __ffs(mask) - 1; mask &= mask - 1;
            st = __shfl_sync(0xffffffffu, cellStart, src);
            cn = __shfl_sync(0xffffffffu, cellCnt,   src);
            if (lane < cn) zp = __ldg(&g_ozp[gbase + st + lane]);
        }
        while (src >= 0) {
            int nsrc = -1, nst = 0, ncn = 0;
            int2 nzp = make_int2(0, 0);
            if (mask) {
                nsrc = __ffs(mask) - 1; mask &= mask - 1;
                nst = __shfl_sync(0xffffffffu, cellStart, nsrc);
                ncn = __shfl_sync(0xffffffffu, cellCnt,   nsrc);
                if (lane < ncn) nzp = __ldg(&g_ozp[gbase + nst + lane]);
            }
            // per-lane best-2 over its points of this cell
            unsigned p1d = 0u, p1q = 0u, p2d = 0u, p2q = 0u;
            float p1z = 0.f, p2z = 0.f;
            if (lane < cn) {
                int s = st + lane;
                float2 xy = sxy[s];
                float pz = __int_as_float(zp.x);
                float dxa = xy.x - ax, dya = xy.y - ay, dza = pz - az;
                float da  = fmaf(dza, dza, fmaf(dya, dya, dxa*dxa));
                float dxb = xy.x - bx, dyb = xy.y - by, dzb = pz - bz;
                float db  = fmaf(dzb, dzb, fmaf(dyb, dyb, dxb*dxb));
                float nm  = fminf(fminf(sdmin[s], da), db);
                sdmin[s] = nm;
                p1d = __float_as_uint(nm);
                p1q = ((0x3FFFu - (unsigned)zp.y) << 14) | (unsigned)s;
                p1z = pz;
            }
            for (int p = lane + 32; p < cn; p += 32) {   // rare: cells with >32 pts
                int s = st + p;
                int2 zp2 = __ldg(&g_ozp[gbase + s]);
                float2 xy = sxy[s];
                float pz = __int_as_float(zp2.x);
                float dxa = xy.x - ax, dya = xy.y - ay, dza = pz - az;
                float da  = fmaf(dza, dza, fmaf(dya, dya, dxa*dxa));
                float dxb = xy.x - bx, dyb = xy.y - by, dzb = pz - bz;
                float db  = fmaf(dzb, dzb, fmaf(dyb, dyb, dxb*dxb));
                float nm  = fminf(fminf(sdmin[s], da), db);
                sdmin[s] = nm;
                unsigned dd = __float_as_uint(nm);
                unsigned qq = ((0x3FFFu - (unsigned)zp2.y) << 14) | (unsigned)s;
                if (dd > p1d || (dd == p1d && qq > p1q)) {
                    p2d = p1d; p2q = p1q; p2z = p1z;
                    p1d = dd;  p1q = qq;  p1z = pz;
                } else if (dd > p2d || (dd == p2d && qq > p2q)) {
                    p2d = dd; p2q = qq; p2z = pz;
                }
            }
            // cell top-1
            unsigned t1d = __reduce_max_sync(0xffffffffu, p1d);
            unsigned t1q = __reduce_max_sync(0xffffffffu, (p1d == t1d) ? p1q : 0u);
            bool w1 = (p1d == t1d && p1q == t1q);
            unsigned wm1 = __ballot_sync(0xffffffffu, w1);
            int l1 = __ffs(wm1) - 1;
            float t1z = __shfl_sync(0xffffffffu, p1z, l1);
            // cell top-2: winner lane contributes its second
            unsigned c2d = w1 ? p2d : p1d;
            unsigned c2q = w1 ? p2q : p1q;
            float    c2z = w1 ? p2z : p1z;
            unsigned t2d = __reduce_max_sync(0xffffffffu, c2d);
            unsigned t2q = __reduce_max_sync(0xffffffffu, (c2d == t2d) ? c2q : 0u);
            unsigned wm2 = __ballot_sync(0xffffffffu, (c2d == t2d && c2q == t2q));
            int l2 = __ffs(wm2) - 1;
            float t2z = __shfl_sync(0xffffffffu, c2z, l2);
            if (lane == src) {
                cD1 = t1d; cQ1 = t1q; cZ1 = t1z;
                cD2 = t2d; cQ2 = t2q; cZ2 = t2z;
            }
            src = nsrc; st = nst; cn = ncn; zp = nzp;
        }

        // ---- warp top-2 over owned cells ----
        unsigned u1d = __reduce_max_sync(0xffffffffu, cD1);
        unsigned u1q = __reduce_max_sync(0xffffffffu, (cD1 == u1d) ? cQ1 : 0u);
        bool W1 = (cD1 == u1d && cQ1 == u1q);
        unsigned e2d = W1 ? cD2 : cD1;
        unsigned e2q = W1 ? cQ2 : cQ1;
        float    e2z = W1 ? cZ2 : cZ1;
        unsigned u2d = __reduce_max_sync(0xffffffffu, e2d);
        unsigned u2q = __reduce_max_sync(0xffffffffu, (e2d == u2d) ? e2q : 0u);
        bool W2 = (e2d == u2d && e2q == u2q);
        if (W1) { s1d[par*32 + wid] = u1d; s1q[par*32 + wid] = u1q; s1z[par*32 + wid] = cZ1; }
        if (W2) { s2d[par*32 + wid] = u2d; s2q[par*32 + wid] = u2q; s2z[par*32 + wid] = e2z; }
        __syncthreads();

        // ---- final top-2 (all warps redundantly) ----
        unsigned f1d = s1d[par*32 + lane], f1q = s1q[par*32 + lane];
        unsigned g1d = __reduce_max_sync(0xffffffffu, f1d);
        unsigned g1q = __reduce_max_sync(0xffffffffu, (f1d == g1d) ? f1q : 0u);
        unsigned wmA = __ballot_sync(0xffffffffu, (f1d == g1d && f1q == g1q));
        int lA = __ffs(wmA) - 1;
        unsigned f2d = s2d[par*32 + lane], f2q = s2q[par*32 + lane];
        unsigned h2d = (lane == lA) ? f2d : f1d;
        unsigned h2q = (lane == lA) ? f2q : f1q;
        unsigned g2d = __reduce_max_sync(0xffffffffu, h2d);
        unsigned g2q = __reduce_max_sync(0xffffffffu, (h2d == g2d) ? h2q : 0u);
        unsigned wmB = __ballot_sync(0xffffffffu, (h2d == g2d && h2q == g2q));
        int lB = __ffs(wmB) - 1;
        float z1 = s1z[par*32 + lA];
        float z2 = (lB == lA) ? s2z[par*32 + lB] : s1z[par*32 + lB];
        int slot1 = (int)(g1q & 0x3FFFu);
        int slot2 = (int)(g2q & 0x3FFFu);
        float2 xy1 = sxy[slot1];
        float2 xy2 = sxy[slot2];
        if (tid == 0) g_sidx[b*SS + t] = 0x3FFF - (int)(g1q >> 14);

        // exact skip-ahead test: p1 provably doesn't lower p2's dmin
        float ddx = xy2.x - xy1.x, ddy = xy2.y - xy1.y, ddz = z2 - z1;
        float d12 = fmaf(ddz, ddz, fmaf(ddy, ddy, ddx*ddx));
        bool cond = (t + 1 < SS) && (g2d != 0u) && (d12 >= __uint_as_float(g2d));
        if (cond && tid == 0) g_sidx[b*SS + t + 1] = 0x3FFF - (int)(g2q >> 14);

        ax = xy1.x; ay = xy1.y; az = z1;
        bx = cond ? xy2.x : ax;
        by = cond ? xy2.y : ay;
        bz = cond ? z2    : az;
        t += cond ? 2 : 1;
        par ^= 1;
    }
}

// ---------------- centers + batch outputs ----------------
__global__ void centers_kernel(float* out_c, float* out_b) {
    int i = blockIdx.x * blockDim.x + threadIdx.x;
    if (i >= MTOT) return;
    int b = i >> 12;
    int gp = b*NN + g_sidx[i];
    float cx = g_posx[gp], cy = g_posy[gp], cz = g_posz[gp];
    g_cx[i] = cx; g_cy[i] = cy; g_cz[i] = cz;
    if (out_c) { out_c[3*i+0] = cx; out_c[3*i+1] = cy; out_c[3*i+2] = cz; }
    if (out_b) { out_b[i] = (float)b; }
}

// ---------------- xw precompute: x @ W1[:16] + b1 ----------------
__global__ void xw_kernel(const float* __restrict__ x,
                          const float* __restrict__ W1,
                          const float* __restrict__ b1) {
    int gid = blockIdx.x * blockDim.x + threadIdx.x;
    if (gid >= BN * 16) return;
    int j  = gid >> 4;
    int c4 = (gid & 15) * 4;
    float a0 = b1[c4+0], a1 = b1[c4+1], a2 = b1[c4+2], a3 = b1[c4+3];
    const float* xr = x + j * FIN;
    #pragma unroll
    for (int k = 0; k < FIN; k++) {
        float xv = xr[k];
        const float* w = W1 + k*64 + c4;
        a0 = fmaf(xv, w[0], a0);
        a1 = fmaf(xv, w[1], a1);
        a2 = fmaf(xv, w[2], a2);
        a3 = fmaf(xv, w[3], a3);
    }
    float4* dst = (float4*)(g_xw + j*64 + c4);
    *dst = make_float4(a0, a1, a2, a3);
}

// ---------------- ball query: warp per center, grid cells, K smallest indices ----------------
__global__ void __launch_bounds__(256) ballq_kernel() {
    __shared__ int cand[8][256];
    __shared__ int scnt_s[8];
    int wid = threadIdx.x >> 5, lane = threadIdx.x & 31;
    int i = blockIdx.x * 8 + wid;
    int b = i >> 12, s = i & 4095;
    float cx = g_cx[i], cy = g_cy[i], cz = g_cz[i];
    if (lane == 0) scnt_s[wid] = 0;
    __syncwarp();

    int icx = (int)(cx * 10.0f); icx = icx < 0 ? 0 : (icx > 9 ? 9 : icx);
    int icy = (int)(cy * 10.0f); icy = icy < 0 ? 0 : (icy > 9 ? 9 : icy);
    int icz = (int)(cz * 10.0f); icz = icz < 0 ? 0 : (icz > 9 ? 9 : icz);
    int zlo = icz > 0 ? icz-1 : 0, zhi = icz < 9 ? icz+1 : 9;
    int ylo = icy > 0 ? icy-1 : 0, yhi = icy < 9 ? icy+1 : 9;
    int xlo = icx > 0 ? icx-1 : 0, xhi = icx < 9 ? icx+1 : 9;

    for (int zz = zlo; zz <= zhi; zz++)
    for (int yy = ylo; yy <= yhi; yy++)
    for (int xx = xlo; xx <= xhi; xx++) {
        int cid = b*NCELL + (zz*10 + yy)*10 + xx;
        int st = g_cellStart[cid];
        int en = st + g_cellCnt[cid];
        for (int idx = st + lane; idx < en; idx += 32) {
            float dx = g_opx[idx] - cx, dy = g_opy[idx] - cy, dz = g_opz[idx] - cz;
            float d2 = fmaf(dz, dz, fmaf(dy, dy, dx*dx));
            int pid = g_opid[idx];
            bool ok = (d2 <= R2) && !(b == 0 && pid == s);  // PyG remove_self_loops
            if (ok) {
                int p = atomicAdd(&scnt_s[wid], 1);
                if (p < 256) cand[wid][p] = pid;
            }
        }
    }
    __syncwarp();
    int m = scnt_s[wid]; if (m > 256) m = 256;
    int take = m < KK ? m : KK;
    // extract 'take' smallest indices (index order = reference sort order)
    for (int r = 0; r < take; r++) {
        int bestkey = 0x7FFFFFFF;
        for (int j = lane; j < m; j += 32) {
            int v = cand[wid][j];          // removed entries hold 0x7FFF (> any pid)
            int key = (v << 8) | j;
            bestkey = min(bestkey, key);
        }
        #pragma unroll
        for (int o = 16; o; o >>= 1)
            bestkey = min(bestkey, __shfl_down_sync(0xffffffffu, bestkey, o));
        bestkey = __shfl_sync(0xffffffffu, bestkey, 0);
        if (lane == 0) {
            g_nbr[i*KK + r] = bestkey >> 8;
            cand[wid][bestkey & 255] = 0x7FFF;
        }
        __syncwarp();
    }
    if (lane == 0) g_cnt[i] = take;
}

// ---------------- fused MLP + max-pool: warp per center, smem h-buffers ----------------
#define MLP_SMEM ((4096 + 8192 + 192 + 64 + 128 + 8*128) * 4)

__global__ void __launch_bounds__(256) mlp_kernel(const float* __restrict__ W1,
                                                  const float* __restrict__ W2,
                                                  const float* __restrict__ b2,
                                                  const float* __restrict__ W3,
                                                  const float* __restrict__ b3,
                                                  float* __restrict__ out_x) {
    extern __shared__ float sm[];
    float* W2s  = sm;            // 64x64
    float* W3s  = W2s + 4096;    // 64x128
    float* W1rs = W3s + 8192;    // rows 16..18 of W1 (rel weights), 3x64
    float* b2s  = W1rs + 192;
    float* b3s  = b2s + 64;
    float* hbuf = b3s + 128;     // 8 warps x (64 h1 + 64 h2)
    int tid = threadIdx.x;
    for (int k = tid; k < 4096; k += 256) W2s[k] = W2[k];
    for (int k = tid; k < 8192; k += 256) W3s[k] = W3[k];
    if (tid < 192) W1rs[tid] = W1[FIN*64 + tid];
    if (tid < 64)  b2s[tid] = b2[tid];
    if (tid < 128) b3s[tid] = b3[tid];
    __syncthreads();

    int wid = tid >> 5, lane = tid & 31;
    float* bufA = hbuf + wid * 128;       // h1 (64)
    float* bufB = bufA + 64;              // h2 (64)
    int i = blockIdx.x * 8 + wid;
    int b = i >> 12;
    int cnt = g_cnt[i];
    float cx = g_cx[i], cy = g_cy[i], cz = g_cz[i];

    float2 w1x = ((const float2*)(W1rs +   0))[lane];
    float2 w1y = ((const float2*)(W1rs +  64))[lane];
    float2 w1z = ((const float2*)(W1rs + 128))[lane];
    float2 bb2 = ((const float2*)b2s)[lane];
    float4 bb3 = ((const float4*)b3s)[lane];

    float m0 = -1e30f, m1 = -1e30f, m2 = -1e30f, m3 = -1e30f;

    for (int e = 0; e <= cnt; e++) {
        // e == cnt -> PyG add_self_loops edge: src flat index == global dst id == i
        int j = (e < cnt) ? (b*NN + g_nbr[i*KK + e]) : i;
        float rx = g_posx[j] - cx, ry = g_posy[j] - cy, rz = g_posz[j] - cz;
        float2 xw = ((const float2*)(g_xw + j*64))[lane];
        float h1a = fmaf(rz, w1z.x, fmaf(ry, w1y.x, fmaf(rx, w1x.x, xw.x)));
        float h1b = fmaf(rz, w1z.y, fmaf(ry, w1y.y, fmaf(rx, w1x.y, xw.y)));
        h1a = fmaxf(h1a, 0.0f);
        h1b = fmaxf(h1b, 0.0f);
        ((float2*)bufA)[lane] = make_float2(h1a, h1b);   // h1[2*lane], h1[2*lane+1]
        __syncwarp();

        float a0 = bb2.x, a1 = bb2.y;
        #pragma unroll
        for (int k4 = 0; k4 < 16; k4++) {                // k = 4*k4 .. 4*k4+3 ascending
            float4 hv = ((const float4*)bufA)[k4];       // broadcast LDS.128
            float2 w0 = ((const float2*)(W2s + (4*k4+0)*64))[lane];
            float2 w1 = ((const float2*)(W2s + (4*k4+1)*64))[lane];
            float2 w2 = ((const float2*)(W2s + (4*k4+2)*64))[lane];
            float2 w3 = ((const float2*)(W2s + (4*k4+3)*64))[lane];
            a0 = fmaf(hv.x, w0.x, a0); a1 = fmaf(hv.x, w0.y, a1);
            a0 = fmaf(hv.y, w1.x, a0); a1 = fmaf(hv.y, w1.y, a1);
            a0 = fmaf(hv.z, w2.x, a0); a1 = fmaf(hv.z, w2.y, a1);
            a0 = fmaf(hv.w, w3.x, a0); a1 = fmaf(hv.w, w3.y, a1);
        }
        float h2a = fmaxf(a0, 0.0f), h2b = fmaxf(a1, 0.0f);
        ((float2*)bufB)[lane] = make_float2(h2a, h2b);
        __syncwarp();

        float c0 = bb3.x, c1 = bb3.y, c2 = bb3.z, c3 = bb3.w;
        #pragma unroll
        for (int k4 = 0; k4 < 16; k4++) {
            float4 hv = ((const float4*)bufB)[k4];
            float4 v0 = ((const float4*)(W3s + (4*k4+0)*128))[lane];
            float4 v1 = ((const float4*)(W3s + (4*k4+1)*128))[lane];
            float4 v2 = ((const float4*)(W3s + (4*k4+2)*128))[lane];
            float4 v3 = ((const float4*)(W3s + (4*k4+3)*128))[lane];
            c0 = fmaf(hv.x, v0.x, c0); c1 = fmaf(hv.x, v0.y, c1);
            c2 = fmaf(hv.x, v0.z, c2); c3 = fmaf(hv.x, v0.w, c3);
            c0 = fmaf(hv.y, v1.x, c0); c1 = fmaf(hv.y, v1.y, c1);
            c2 = fmaf(hv.y, v1.z, c2); c3 = fmaf(hv.y, v1.w, c3);
            c0 = fmaf(hv.z, v2.x, c0); c1 = fmaf(hv.z, v2.y, c1);
            c2 = fmaf(hv.z, v2.z, c2); c3 = fmaf(hv.z, v2.w, c3);
            c0 = fmaf(hv.w, v3.x, c0); c1 = fmaf(hv.w, v3.y, c1);
            c2 = fmaf(hv.w, v3.z, c2); c3 = fmaf(hv.w, v3.w, c3);
        }
        m0 = fmaxf(m0, c0); m1 = fmaxf(m1, c1);
        m2 = fmaxf(m2, c2); m3 = fmaxf(m3, c3);
    }
    ((float4*)(out_x + i*128))[lane] = make_float4(m0, m1, m2, m3);
}

// ---------------- host launcher ----------------
extern "C" void kernel_launch(void* const* d_in, const int* in_sizes, int n_in,
                              void* d_out, int out_size) {
    const float* x   = (const float*)d_in[0];
    const float* pos = (const float*)d_in[1];
    // d_in[2] = batch (int32) -- derivable, unused
    const float* W1  = (const float*)d_in[3];
    const float* b1  = (const float*)d_in[4];
    const float* W2  = (const float*)d_in[5];
    const float* b2  = (const float*)d_in[6];
    const float* W3  = (const float*)d_in[7];
    const float* b3  = (const float*)d_in[8];

    float* out   = (float*)d_out;
    float* out_c = (out_size >= MTOT*131) ? out + MTOT*128 : nullptr;
    float* out_b = (out_size >= MTOT*132) ? out + MTOT*131 : nullptr;

    cudaFuncSetAttribute(fps_top2_kernel, cudaFuncAttributeMaxDynamicSharedMemorySize, FPS8_SMEM);
    cudaFuncSetAttribute(mlp_kernel, cudaFuncAttributeMaxDynamicSharedMemorySize, MLP_SMEM);

    prep_kernel    <<<(BN + 255)/256, 256>>>(pos);
    count_kernel   <<<(BN + 255)/256, 256>>>();
    scan_kernel    <<<1, 32>>>();
    scatter_kernel <<<(BN + 255)/256, 256>>>();
    gather_kernel  <<<(BN + 255)/256, 256>>>();
    xw_kernel      <<<(BN*16 + 127)/128, 128>>>(x, W1, b1);
    fps_top2_kernel<<<BB, 1024, FPS8_SMEM>>>();
    centers_kernel <<<(MTOT + 255)/256, 256>>>(out_c, out_b);
    ballq_kernel   <<<MTOT/8, 256>>>();
    mlp_kernel     <<<MTOT/8, 256, MLP_SMEM>>>(W1, W2, b2, W3, b3, out);
}